// round 16
// baseline (speedup 1.0000x reference)
#include <cuda_runtime.h>
#include <cuda_bf16.h>
#include <cstdint>

// TemporalCooccurrenceMatrix — round 16: exp2-domain weight.
// w(pair) = exp(-(l1-l2)^2/4 - |t1-t2|/5) computed as one EX2 per matched pair:
//   t' = t * (log2e/5);  arg = -C1*d^2 - |t'_i - t'_j|;  w = 2^arg,  C1 = log2e/4.
// Kills: dvals table, float2 S table (-> 4B t' table), all decode/row-build MUFU.
// Shape unchanged from R15: 512 CTAs, 288 thr, 2 thr/target, packed vk,
// single deferred rare path, tanh.approx, direct symmetric epilogue.

#define BDIM 288              // 2 threads x 129 targets = 258 active

#define TSCALE 0.2885390081777927f   // 0.2 * log2(e)
#define C1     0.3606737602222409f   // 0.25 * log2(e)

__device__ __forceinline__ float tanh_approx(float x) {
    float r;
    asm("tanh.approx.f32 %0, %1;" : "=f"(r) : "f"(x));
    return r;
}
__device__ __forceinline__ float exp2_approx(float x) {
    float r;
    asm("ex2.approx.f32 %0, %1;" : "=f"(r) : "f"(x));
    return r;
}

__global__ __launch_bounds__(BDIM)
void cooc_fused(const void* __restrict__ nodes_raw,
                const void* __restrict__ masks_raw,
                const float* __restrict__ times,
                float* __restrict__ out)
{
    const int r   = blockIdx.x;   // 0..63
    const int b   = blockIdx.y;   // 0..7
    const int tid = threadIdx.x;

    const int wA = r, wB = 127 - r;
    const int nA = 128 - r;       // row-A targets (w2 in [r,127]); nB = r+1

    __shared__ unsigned int nmA[33], nmB[33];   // [32] stays 0 (sentinel)
    __shared__ float        sTA[32], sTB[32];   // t' per row pos; [20..31] = +INF
    __shared__ int          s_n64, s_m32;

    // ---- target identity ----
    const int  pair   = tid >> 1;               // 0..143 (129 real)
    const int  half   = tid & 1;
    const bool active = (pair < 129);
    const bool rowA   = active ? (pair < nA) : true;
    int w2 = rowA ? (wA + (active ? pair : 0)) : (wB + (pair - nA));
    if (!active) w2 = 127;                      // safe addresses, result discarded
    const int jbase = (b * 128 + w2) * 20 + half * 10;

    // ---- phase A: detection + smem init + independent time prefetch ----
    if (tid < 32) {                             // warp 0: dtype detection
        const unsigned int*  nw = (const unsigned int*)nodes_raw;
        const unsigned char* mb = (const unsigned char*)masks_raw;
        unsigned int oddw = nw[2 * tid + 1];             // int64 LE hi words all 0
        unsigned char b0 = mb[tid], b1 = mb[32 + tid];   // int32-bool: k%4!=0 zero
        int nviol = (oddw != 0u);
        int mviol = (((tid & 3) != 0) && b0 != 0) |
                    ((((32 + tid) & 3) != 0) && b1 != 0);
        unsigned int vn = __ballot_sync(0xFFFFFFFFu, nviol);
        unsigned int vm = __ballot_sync(0xFFFFFFFFu, mviol);
        if (tid == 0) { s_n64 = (vn == 0u); s_m32 = (vm == 0u); }
    }
    if (tid >= 64  && tid < 97)  nmA[tid - 64] = 0u;
    if (tid >= 97  && tid < 130) nmB[tid - 97] = 0u;
    if (tid >= 130 && tid < 142) sTA[20 + tid - 130] = __int_as_float(0x7f800000);
    if (tid >= 142 && tid < 154) sTB[20 + tid - 142] = __int_as_float(0x7f800000);

    // target times: 10 floats, 8B-aligned -> 5 independent LDG.64 (MLP)
    float2 t2[5];
    {
        const float2* tp = (const float2*)(times + jbase);
#pragma unroll
        for (int q = 0; q < 5; q++) t2[q] = tp[q];
    }
    __syncthreads();

    const int n64 = s_n64, m32 = s_m32;
    const unsigned int*  n32p = (const unsigned int*)nodes_raw;
    const unsigned char* mbp  = (const unsigned char*)masks_raw;
    const unsigned int*  m32p = (const unsigned int*)masks_raw;

    // ---- phase B: row tables + packed target node/mask ----
    if (tid < 20) {
        const int i = (b * 128 + wA) * 20 + tid;
        int  v = (int)(n64 ? n32p[i * 2] : n32p[i]) & 31;
        bool m = m32 ? (m32p[i] != 0u) : (mbp[i] != 0);
        sTA[tid] = times[i] * TSCALE;
        if (m) atomicOr(&nmA[v], 1u << tid);
    } else if (tid >= 32 && tid < 52) {
        const int l = tid - 32;
        const int i = (b * 128 + wB) * 20 + l;
        int  v = (int)(n64 ? n32p[i * 2] : n32p[i]) & 31;
        bool m = m32 ? (m32p[i] != 0u) : (mbp[i] != 0);
        sTB[l] = times[i] * TSCALE;
        if (m) atomicOr(&nmB[v], 1u << l);
    }

    // pack 10 target values (0..31, or 32 if masked) into two words, 6b each
    unsigned int vkp0 = 0u, vkp1 = 0u;
#pragma unroll
    for (int k = 0; k < 10; k++) {
        unsigned int v = n64 ? (n32p[(jbase + k) * 2] & 31u)
                             : (n32p[jbase + k] & 31u);
        bool m = m32 ? (m32p[jbase + k] != 0u) : (mbp[jbase + k] != 0);
        if (!m) v = 32u;
        if (k < 5) vkp0 |= v << (6 * k);
        else       vkp1 |= v << (6 * (k - 5));
    }

    // target t' (scaled times; no MUFU)
    float tjs[10];
#pragma unroll
    for (int q = 0; q < 5; q++) {
        tjs[2 * q]     = t2[q].x * TSCALE;
        tjs[2 * q + 1] = t2[q].y * TSCALE;
    }
    __syncthreads();

    // ---- phase C: straight-line 2-slot loop, single deferred rare path ----
    const unsigned int* NM = rowA ? nmA : nmB;
    const float*        T  = rowA ? sTA : sTB;
    const int ljbase = half * 10;

    float a0 = 0.0f, a1 = 0.0f;
    unsigned int restflags = 0u;
#pragma unroll
    for (int k = 0; k < 10; k++) {
        const unsigned int vkk = (k < 5 ? (vkp0 >> (6 * k)) : (vkp1 >> (6 * (k - 5)))) & 63u;
        unsigned int bits = NM[vkk];
        const float tjk = tjs[k];
        const int lj = ljbase + k;

        int li0 = __ffs(bits) - 1;               // empty -> -1 -> T[31]=+INF -> w=0
        unsigned int b1m = bits & (bits - 1);
        int li1 = __ffs(b1m) - 1;
        restflags |= (b1m & (b1m - 1)) ? (1u << k) : 0u;
        {
            float ti = T[li0 & 31];
            float dF = (float)(li0 - lj);
            float ad = fabsf(tjk - ti);
            a0 += exp2_approx(fmaf(dF * dF, -C1, -ad));
        }
        {
            float ti = T[li1 & 31];
            float dF = (float)(li1 - lj);
            float ad = fabsf(tjk - ti);
            a1 += exp2_approx(fmaf(dF * dF, -C1, -ad));
        }
    }

    if (restflags) {                             // multiplicity >= 3 (rare)
#pragma unroll 1
        do {
            int k = __ffs(restflags) - 1;
            restflags &= restflags - 1;
            const unsigned int vkk =
                (k < 5 ? (vkp0 >> (6 * k)) : (vkp1 >> (6 * (k - 5)))) & 63u;
            unsigned int bits = NM[vkk];
            bits &= bits - 1;                    // drop slot 0
            bits &= bits - 1;                    // drop slot 1
            const float tjk = tjs[k];
            const int lj = ljbase + k;
#pragma unroll 1
            do {
                int li = __ffs(bits) - 1;
                bits &= bits - 1;
                float ti = T[li];
                float dF = (float)(li - lj);
                float ad = fabsf(tjk - ti);
                a0 += exp2_approx(fmaf(dF * dF, -C1, -ad));
            } while (bits);
        } while (restflags);
    }

    // ---- combine halves, tanh, symmetric store ----
    float a = a0 + a1;
    a += __shfl_xor_sync(0xFFFFFFFFu, a, 1);
    if (active && half == 0) {
        const int w1 = rowA ? wA : wB;
        float v = tanh_approx(fminf(a, 10.0f));  // a >= 0
        out[(b * 128 + w1) * 128 + w2] = v;
        out[(b * 128 + w2) * 128 + w1] = v;
    }
}

extern "C" void kernel_launch(void* const* d_in, const int* in_sizes, int n_in,
                              void* d_out, int out_size)
{
    const void*  nodes = d_in[0];
    const void*  masks = d_in[1];
    const float* times = (const float*)d_in[2];
    float*       out   = (float*)d_out;

    dim3 grid(64, 8);
    cooc_fused<<<grid, BDIM>>>(nodes, masks, times, out);
}